// round 1
// baseline (speedup 1.0000x reference)
#include <cuda_runtime.h>
#include <cuda_bf16.h>
#include <cstdint>

#define NN 100000
#define EE 1600000
#define CIN 128
#define CC 64

// ---------------- scratch (device globals; no allocation allowed) ----------
__device__ float g_h [NN * CC];
__device__ float g_t1[NN * CC];
__device__ float g_t2[NN * CC];
__device__ float g_t3[NN * CC];
__device__ int   g_src[EE];
__device__ int   g_dst[EE];
__device__ int   g_flag[1];

// ---------------- index width detection + normalization --------------------
// If the harness hands us int64 indices (values < 2^31, nonneg), every odd
// 32-bit word of the buffer is 0. 64 random int32 indices in [0,1e5) being all
// zero is impossible, so this is a safe discriminator.
__global__ void detect_kernel(const unsigned int* p) {
    if (threadIdx.x == 0 && blockIdx.x == 0) {
        int is64 = 1;
        for (int i = 1; i < 128; i += 2)
            if (p[i] != 0u) { is64 = 0; break; }
        g_flag[0] = is64;
    }
}

__global__ void convert_kernel(const void* srcp, const void* dstp) {
    int e = blockIdx.x * blockDim.x + threadIdx.x;
    if (e >= EE) return;
    int f = g_flag[0];
    if (f) {
        g_src[e] = (int)((const long long*)srcp)[e];
        g_dst[e] = (int)((const long long*)dstp)[e];
    } else {
        g_src[e] = ((const int*)srcp)[e];
        g_dst[e] = ((const int*)dstp)[e];
    }
}

// ---------------- zero the SpMM accumulators --------------------------------
__global__ void zero_kernel() {
    const int total = NN * CC / 4;
    float4 z = make_float4(0.f, 0.f, 0.f, 0.f);
    float4* a = (float4*)g_t1;
    float4* b = (float4*)g_t2;
    float4* c = (float4*)g_t3;
    for (int i = blockIdx.x * blockDim.x + threadIdx.x; i < total;
         i += gridDim.x * blockDim.x) {
        a[i] = z; b[i] = z; c[i] = z;
    }
}

// ---------------- input GEMM: h = relu(x @ W_in + b_in) ---------------------
// One warp per node; lane owns channels (lane, lane+32). W_in (32KB) in smem.
__global__ void gemm_in_kernel(const float* __restrict__ x,
                               const float* __restrict__ Win,
                               const float* __restrict__ bin) {
    __shared__ float Ws[CIN * CC];
    __shared__ float bs[CC];
    for (int i = threadIdx.x; i < CIN * CC; i += blockDim.x) Ws[i] = Win[i];
    if (threadIdx.x < CC) bs[threadIdx.x] = bin[threadIdx.x];
    __syncthreads();

    int lane = threadIdx.x & 31;
    int gw = (blockIdx.x * blockDim.x + threadIdx.x) >> 5;
    int nw = (gridDim.x * blockDim.x) >> 5;
    for (int n = gw; n < NN; n += nw) {
        const float4* xr = (const float4*)(x + (size_t)n * CIN);
        float a0 = bs[lane], a1 = bs[lane + 32];
#pragma unroll
        for (int k4 = 0; k4 < CIN / 4; k4++) {
            float4 xv = __ldg(&xr[k4]);
            int k = k4 * 4;
            a0 = fmaf(xv.x, Ws[(k + 0) * CC + lane], a0);
            a1 = fmaf(xv.x, Ws[(k + 0) * CC + lane + 32], a1);
            a0 = fmaf(xv.y, Ws[(k + 1) * CC + lane], a0);
            a1 = fmaf(xv.y, Ws[(k + 1) * CC + lane + 32], a1);
            a0 = fmaf(xv.z, Ws[(k + 2) * CC + lane], a0);
            a1 = fmaf(xv.z, Ws[(k + 2) * CC + lane + 32], a1);
            a0 = fmaf(xv.w, Ws[(k + 3) * CC + lane], a0);
            a1 = fmaf(xv.w, Ws[(k + 3) * CC + lane + 32], a1);
        }
        g_h[(size_t)n * CC + lane]      = fmaxf(a0, 0.f);
        g_h[(size_t)n * CC + lane + 32] = fmaxf(a1, 0.f);
    }
}

// ---------------- SpMM: out[dst] += val * in[src] ---------------------------
// 16 threads per edge, float4 per thread, vector atomicAdd (sm_90+ RED.128).
template <int S>
__global__ void spmm_kernel(const float* __restrict__ vals) {
    const float* __restrict__ in = (S == 0) ? g_h : (S == 1) ? g_t1 : g_t2;
    float* out = (S == 0) ? g_t1 : (S == 1) ? g_t2 : g_t3;

    long long idx = (long long)blockIdx.x * blockDim.x + threadIdx.x;
    if (idx >= (long long)EE * 16) return;
    int e = (int)(idx >> 4);
    int q = (int)(idx & 15);

    float v = __ldg(&vals[e]);
    int s = g_src[e];
    int d = g_dst[e];
    const float4 hv = *(const float4*)(in + (size_t)s * CC + q * 4);
    float4 r = make_float4(v * hv.x, v * hv.y, v * hv.z, v * hv.w);
    atomicAdd((float4*)(out + (size_t)d * CC + q * 4), r);
}

// ---------------- fused epilogue --------------------------------------------
__device__ __forceinline__ void matvec64(float va, float vb,
                                         const float* __restrict__ Ws,
                                         const float* __restrict__ bs,
                                         int lane, float& o0, float& o1) {
    float a0 = bs[lane], a1 = bs[lane + 32];
#pragma unroll
    for (int k = 0; k < 32; k++) {
        float vk = __shfl_sync(0xffffffffu, va, k);
        a0 = fmaf(vk, Ws[k * CC + lane], a0);
        a1 = fmaf(vk, Ws[k * CC + lane + 32], a1);
    }
#pragma unroll
    for (int k = 0; k < 32; k++) {
        float vk = __shfl_sync(0xffffffffu, vb, k);
        a0 = fmaf(vk, Ws[(k + 32) * CC + lane], a0);
        a1 = fmaf(vk, Ws[(k + 32) * CC + lane + 32], a1);
    }
    o0 = a0; o1 = a1;
}

__device__ __forceinline__ float warpsum(float v) {
    v += __shfl_xor_sync(0xffffffffu, v, 16);
    v += __shfl_xor_sync(0xffffffffu, v, 8);
    v += __shfl_xor_sync(0xffffffffu, v, 4);
    v += __shfl_xor_sync(0xffffffffu, v, 2);
    v += __shfl_xor_sync(0xffffffffu, v, 1);
    return v;
}

// shared layout offsets (floats)
#define OFF_WB  0
#define OFF_WX  4096
#define OFF_W1  8192
#define OFF_W2  12288
#define OFF_W3  14336
#define OFF_VC  14400
#define OFF_BWB 14464
#define OFF_BWX 14528
#define OFF_B1  14592
#define OFF_B2  14656
#define OFF_B3  14688
#define EPI_SMEM_FLOATS 14720
#define EPI_SMEM_BYTES (EPI_SMEM_FLOATS * 4)

__global__ void epilogue_kernel(const float* __restrict__ thetas,
                                const float* __restrict__ Wb, const float* __restrict__ bWb,
                                const float* __restrict__ Wx, const float* __restrict__ bWx,
                                const float* __restrict__ vc,
                                const float* __restrict__ W1, const float* __restrict__ b1,
                                const float* __restrict__ W2, const float* __restrict__ b2,
                                const float* __restrict__ W3, const float* __restrict__ b3,
                                float* __restrict__ out) {
    extern __shared__ float sm[];
    int t = threadIdx.x;
    for (int i = t; i < 4096; i += blockDim.x) {
        sm[OFF_WB + i] = Wb[i];
        sm[OFF_WX + i] = Wx[i];
        sm[OFF_W1 + i] = W1[i];
    }
    for (int i = t; i < 2048; i += blockDim.x) sm[OFF_W2 + i] = W2[i];
    if (t < 64) {
        sm[OFF_W3 + t]  = W3[t];
        sm[OFF_VC + t]  = vc[t];
        sm[OFF_BWB + t] = bWb[t];
        sm[OFF_BWX + t] = bWx[t];
        sm[OFF_B1 + t]  = b1[t];
    }
    if (t < 32) sm[OFF_B2 + t] = b2[t];
    if (t < 2)  sm[OFF_B3 + t] = b3[t];
    __syncthreads();

    // cf[f][k] = (thetas @ BCOEF)[f][k]
    float t00 = thetas[0], t01 = thetas[1], t02 = thetas[2], t03 = thetas[3];
    float t10 = thetas[4], t11 = thetas[5], t12 = thetas[6], t13 = thetas[7];
    float c00 = t00;
    float c01 = -3.f * t00 + 3.f * t01;
    float c02 =  3.f * t00 - 6.f * t01 + 3.f * t02;
    float c03 = -1.f * t00 + 3.f * t01 - 3.f * t02 + t03;
    float c10 = t10;
    float c11 = -3.f * t10 + 3.f * t11;
    float c12 =  3.f * t10 - 6.f * t11 + 3.f * t12;
    float c13 = -1.f * t10 + 3.f * t11 - 3.f * t12 + t13;

    const float* sWb = sm + OFF_WB;
    const float* sWx = sm + OFF_WX;
    const float* sW1 = sm + OFF_W1;
    const float* sW2 = sm + OFF_W2;
    const float* sW3 = sm + OFF_W3;
    const float* svc = sm + OFF_VC;

    int lane = threadIdx.x & 31;
    int gw = (blockIdx.x * blockDim.x + threadIdx.x) >> 5;
    int nw = (gridDim.x * blockDim.x) >> 5;

    for (int n = gw; n < NN; n += nw) {
        size_t base = (size_t)n * CC;
        float ha  = g_h [base + lane], hb  = g_h [base + lane + 32];
        float x1a = g_t1[base + lane], x1b = g_t1[base + lane + 32];
        float x2a = g_t2[base + lane], x2b = g_t2[base + lane + 32];
        float x3a = g_t3[base + lane], x3b = g_t3[base + lane + 32];

        // poly[f] = cf[f] . (Tx0..Tx3)
        float p0a = c00 * ha + c01 * x1a + c02 * x2a + c03 * x3a;
        float p0b = c00 * hb + c01 * x1b + c02 * x2b + c03 * x3b;
        float p1a = c10 * ha + c11 * x1a + c12 * x2a + c13 * x3a;
        float p1b = c10 * hb + c11 * x1b + c12 * x2b + c13 * x3b;

        // attention
        float pp0a, pp0b, pp1a, pp1b, xpa, xpb;
        matvec64(p0a, p0b, sWb, sm + OFF_BWB, lane, pp0a, pp0b);
        matvec64(p1a, p1b, sWb, sm + OFF_BWB, lane, pp1a, pp1b);
        matvec64(ha, hb, sWx, sm + OFF_BWX, lane, xpa, xpb);

        float s0 = warpsum(tanhf(pp0a + xpa) * svc[lane] +
                           tanhf(pp0b + xpb) * svc[lane + 32]);
        float s1 = warpsum(tanhf(pp1a + xpa) * svc[lane] +
                           tanhf(pp1b + xpb) * svc[lane + 32]);
        float m = fmaxf(s0, s1);
        float e0 = expf(s0 - m), e1 = expf(s1 - m);
        float inv = 1.f / (e0 + e1);
        float a0 = e0 * inv, a1 = e1 * inv;

        float ra = a0 * p0a + a1 * p1a;
        float rb = a0 * p0b + a1 * p1b;

        // classifier head
        float y1a, y1b;
        matvec64(ra, rb, sW1, sm + OFF_B1, lane, y1a, y1b);
        y1a = fmaxf(y1a, 0.f); y1b = fmaxf(y1b, 0.f);

        // y2[c] for c = lane (32 outputs)
        float acc = sm[OFF_B2 + lane];
#pragma unroll
        for (int k = 0; k < 32; k++) {
            float vk = __shfl_sync(0xffffffffu, y1a, k);
            acc = fmaf(vk, sW2[k * 32 + lane], acc);
        }
#pragma unroll
        for (int k = 0; k < 32; k++) {
            float vk = __shfl_sync(0xffffffffu, y1b, k);
            acc = fmaf(vk, sW2[(k + 32) * 32 + lane], acc);
        }
        float y2 = fmaxf(acc, 0.f);

        // out[j] = b3[j] + sum_k y2[k] * W3[k][j]
        float q0 = y2 * sW3[lane * 2 + 0];
        float q1 = y2 * sW3[lane * 2 + 1];
        q0 = warpsum(q0);
        q1 = warpsum(q1);
        if (lane == 0) {
            out[(size_t)n * 2 + 0] = sm[OFF_B3 + 0] + q0;
            out[(size_t)n * 2 + 1] = sm[OFF_B3 + 1] + q1;
        }
    }
}

// ---------------- launch ----------------------------------------------------
extern "C" void kernel_launch(void* const* d_in, const int* in_sizes, int n_in,
                              void* d_out, int out_size) {
    const float* x      = (const float*)d_in[0];
    const void*  esrc   = d_in[1];
    const void*  edst   = d_in[2];
    const float* evals  = (const float*)d_in[3];
    const float* Win    = (const float*)d_in[4];
    const float* bin    = (const float*)d_in[5];
    const float* thetas = (const float*)d_in[6];
    const float* Wb     = (const float*)d_in[7];
    const float* bWb    = (const float*)d_in[8];
    const float* Wx     = (const float*)d_in[9];
    const float* bWx    = (const float*)d_in[10];
    const float* vc     = (const float*)d_in[11];
    const float* W1     = (const float*)d_in[12];
    const float* b1     = (const float*)d_in[13];
    const float* W2     = (const float*)d_in[14];
    const float* b2     = (const float*)d_in[15];
    const float* W3     = (const float*)d_in[16];
    const float* b3     = (const float*)d_in[17];
    float* out = (float*)d_out;

    cudaFuncSetAttribute(epilogue_kernel,
                         cudaFuncAttributeMaxDynamicSharedMemorySize,
                         EPI_SMEM_BYTES);

    detect_kernel<<<1, 32>>>((const unsigned int*)esrc);
    convert_kernel<<<(EE + 255) / 256, 256>>>(esrc, edst);
    zero_kernel<<<2048, 256>>>();
    gemm_in_kernel<<<1184, 256>>>(x, Win, bin);

    const long long spmm_threads = (long long)EE * 16;
    const int spmm_blocks = (int)((spmm_threads + 255) / 256);
    spmm_kernel<0><<<spmm_blocks, 256>>>(evals);
    spmm_kernel<1><<<spmm_blocks, 256>>>(evals);
    spmm_kernel<2><<<spmm_blocks, 256>>>(evals);

    epilogue_kernel<<<444, 256, EPI_SMEM_BYTES>>>(
        thetas, Wb, bWb, Wx, bWx, vc, W1, b1, W2, b2, W3, b3, out);
}

// round 3
// speedup vs baseline: 1.3868x; 1.3868x over previous
#include <cuda_runtime.h>
#include <cuda_bf16.h>
#include <cstdint>

#define NN 100000
#define EE 1600000
#define CIN 128
#define CC 64
#define NB_SCAN 196   // ceil(NN/512)

// ---------------- scratch (device globals; no allocation allowed) ----------
__device__ float g_h [NN * CC];
__device__ float g_t1[NN * CC];
__device__ float g_t2[NN * CC];
__device__ float g_t3[NN * CC];
__device__ int   g_src[EE];
__device__ int   g_dst[EE];
__device__ int2  g_edge[EE];      // sorted-by-dst: {src, __float_as_int(val)}
__device__ int   g_rowptr[NN + 1];
__device__ int   g_cnt[NN];       // histogram, then running scatter offsets
__device__ int   g_bsum[NB_SCAN];
__device__ int   g_bsumex[NB_SCAN];
__device__ int   g_flag[1];

// ---------------- index width detection ------------------------------------
// int64 indices with values < 2^31: every odd 32-bit word is 0. 64 random
// int32 indices in [0,1e5) being all zero is impossible.
__global__ void detect_kernel(const unsigned int* p) {
    if (threadIdx.x == 0 && blockIdx.x == 0) {
        int is64 = 1;
        for (int i = 1; i < 128; i += 2)
            if (p[i] != 0u) { is64 = 0; break; }
        g_flag[0] = is64;
    }
}

__global__ void zero_cnt_kernel() {
    int i = blockIdx.x * blockDim.x + threadIdx.x;
    if (i < NN) g_cnt[i] = 0;
}

__global__ void convert_hist_kernel(const void* srcp, const void* dstp) {
    int e = blockIdx.x * blockDim.x + threadIdx.x;
    if (e >= EE) return;
    int s, d;
    if (g_flag[0]) {
        s = (int)((const long long*)srcp)[e];
        d = (int)((const long long*)dstp)[e];
    } else {
        s = ((const int*)srcp)[e];
        d = ((const int*)dstp)[e];
    }
    g_src[e] = s;
    g_dst[e] = d;
    atomicAdd(&g_cnt[d], 1);
}

// ---------------- 2-level exclusive scan over g_cnt ------------------------
__global__ void scan_block_kernel() {   // 512 threads per block
    __shared__ int s[512];
    int tid = threadIdx.x;
    int i = blockIdx.x * 512 + tid;
    int v = (i < NN) ? g_cnt[i] : 0;
    s[tid] = v;
    __syncthreads();
#pragma unroll
    for (int off = 1; off < 512; off <<= 1) {
        int t = (tid >= off) ? s[tid - off] : 0;
        __syncthreads();
        s[tid] += t;
        __syncthreads();
    }
    if (i < NN) g_rowptr[i] = s[tid] - v;
    if (tid == 511) g_bsum[blockIdx.x] = s[511];
}

__global__ void scan_bsum_kernel() {    // single block, 256 threads
    __shared__ int s[256];
    int tid = threadIdx.x;
    int v = (tid < NB_SCAN) ? g_bsum[tid] : 0;
    s[tid] = v;
    __syncthreads();
#pragma unroll
    for (int off = 1; off < 256; off <<= 1) {
        int t = (tid >= off) ? s[tid - off] : 0;
        __syncthreads();
        s[tid] += t;
        __syncthreads();
    }
    if (tid < NB_SCAN) g_bsumex[tid] = s[tid] - v;
}

__global__ void add_offsets_kernel() {
    int i = blockIdx.x * blockDim.x + threadIdx.x;
    if (i < NN) {
        int r = g_rowptr[i] + g_bsumex[i >> 9];
        g_rowptr[i] = r;
        g_cnt[i] = r;
    }
    if (i == 0) g_rowptr[NN] = EE;
}

__global__ void scatter_kernel(const float* __restrict__ vals) {
    int e = blockIdx.x * blockDim.x + threadIdx.x;
    if (e >= EE) return;
    int d = g_dst[e];
    int pos = atomicAdd(&g_cnt[d], 1);
    g_edge[pos] = make_int2(g_src[e], __float_as_int(vals[e]));
}

// ---------------- input GEMM: h = relu(x @ W_in + b_in) ---------------------
// 4 nodes per warp iter; lane owns channels (lane, lane+32) packed as float2.
__global__ void gemm_in_kernel(const float* __restrict__ x,
                               const float* __restrict__ Win,
                               const float* __restrict__ bin) {
    __shared__ float2 Ws[CIN * 32];
    __shared__ float bs[CC];
    for (int i = threadIdx.x; i < CIN * 32; i += blockDim.x) {
        int k = i >> 5, l = i & 31;
        Ws[i] = make_float2(Win[k * CC + l], Win[k * CC + l + 32]);
    }
    if (threadIdx.x < CC) bs[threadIdx.x] = bin[threadIdx.x];
    __syncthreads();

    int lane = threadIdx.x & 31;
    int gw = (blockIdx.x * blockDim.x + threadIdx.x) >> 5;
    int nw = (gridDim.x * blockDim.x) >> 5;
    const int NG = NN / 4;   // 25000, exact

    for (int g = gw; g < NG; g += nw) {
        int n0 = g * 4;
        const float4* xr0 = (const float4*)(x + (size_t)(n0 + 0) * CIN);
        const float4* xr1 = (const float4*)(x + (size_t)(n0 + 1) * CIN);
        const float4* xr2 = (const float4*)(x + (size_t)(n0 + 2) * CIN);
        const float4* xr3 = (const float4*)(x + (size_t)(n0 + 3) * CIN);
        float b0 = bs[lane], b1 = bs[lane + 32];
        float a00 = b0, a01 = b1, a10 = b0, a11 = b1;
        float a20 = b0, a21 = b1, a30 = b0, a31 = b1;
#pragma unroll 4
        for (int k4 = 0; k4 < CIN / 4; k4++) {
            float xa[4], xb[4], xc[4], xd[4];
            *(float4*)xa = __ldg(&xr0[k4]);
            *(float4*)xb = __ldg(&xr1[k4]);
            *(float4*)xc = __ldg(&xr2[k4]);
            *(float4*)xd = __ldg(&xr3[k4]);
#pragma unroll
            for (int kk = 0; kk < 4; kk++) {
                float2 w = Ws[(k4 * 4 + kk) * 32 + lane];
                a00 = fmaf(xa[kk], w.x, a00); a01 = fmaf(xa[kk], w.y, a01);
                a10 = fmaf(xb[kk], w.x, a10); a11 = fmaf(xb[kk], w.y, a11);
                a20 = fmaf(xc[kk], w.x, a20); a21 = fmaf(xc[kk], w.y, a21);
                a30 = fmaf(xd[kk], w.x, a30); a31 = fmaf(xd[kk], w.y, a31);
            }
        }
        g_h[(size_t)(n0 + 0) * CC + lane]      = fmaxf(a00, 0.f);
        g_h[(size_t)(n0 + 0) * CC + lane + 32] = fmaxf(a01, 0.f);
        g_h[(size_t)(n0 + 1) * CC + lane]      = fmaxf(a10, 0.f);
        g_h[(size_t)(n0 + 1) * CC + lane + 32] = fmaxf(a11, 0.f);
        g_h[(size_t)(n0 + 2) * CC + lane]      = fmaxf(a20, 0.f);
        g_h[(size_t)(n0 + 2) * CC + lane + 32] = fmaxf(a21, 0.f);
        g_h[(size_t)(n0 + 3) * CC + lane]      = fmaxf(a30, 0.f);
        g_h[(size_t)(n0 + 3) * CC + lane + 32] = fmaxf(a31, 0.f);
    }
}

// ---------------- CSR SpMM (no atomics) -------------------------------------
// One warp per dst row. 4-edge batches with all loads front-issued for MLP.
template <int S>
__global__ void spmm_csr_kernel() {
    const float* __restrict__ in = (S == 0) ? g_h : (S == 1) ? g_t1 : g_t2;
    float* __restrict__ out = (S == 0) ? g_t1 : (S == 1) ? g_t2 : g_t3;

    int lane = threadIdx.x & 31;
    int gw = (blockIdx.x * blockDim.x + threadIdx.x) >> 5;
    int nw = (gridDim.x * blockDim.x) >> 5;

    for (int n = gw; n < NN; n += nw) {
        int beg = g_rowptr[n];
        int end = g_rowptr[n + 1];
        float a0 = 0.f, a1 = 0.f;
        int j = beg;
        for (; j + 3 < end; j += 4) {
            int2 e0 = __ldg(&g_edge[j + 0]);
            int2 e1 = __ldg(&g_edge[j + 1]);
            int2 e2 = __ldg(&g_edge[j + 2]);
            int2 e3 = __ldg(&g_edge[j + 3]);
            const float* r0 = in + (size_t)e0.x * CC;
            const float* r1 = in + (size_t)e1.x * CC;
            const float* r2 = in + (size_t)e2.x * CC;
            const float* r3 = in + (size_t)e3.x * CC;
            float u00 = __ldg(r0 + lane), u01 = __ldg(r0 + lane + 32);
            float u10 = __ldg(r1 + lane), u11 = __ldg(r1 + lane + 32);
            float u20 = __ldg(r2 + lane), u21 = __ldg(r2 + lane + 32);
            float u30 = __ldg(r3 + lane), u31 = __ldg(r3 + lane + 32);
            float v0 = __int_as_float(e0.y);
            float v1 = __int_as_float(e1.y);
            float v2 = __int_as_float(e2.y);
            float v3 = __int_as_float(e3.y);
            a0 = fmaf(v0, u00, a0); a1 = fmaf(v0, u01, a1);
            a0 = fmaf(v1, u10, a0); a1 = fmaf(v1, u11, a1);
            a0 = fmaf(v2, u20, a0); a1 = fmaf(v2, u21, a1);
            a0 = fmaf(v3, u30, a0); a1 = fmaf(v3, u31, a1);
        }
        for (; j < end; j++) {
            int2 e0 = __ldg(&g_edge[j]);
            const float* r0 = in + (size_t)e0.x * CC;
            float v0 = __int_as_float(e0.y);
            a0 = fmaf(v0, __ldg(r0 + lane), a0);
            a1 = fmaf(v0, __ldg(r0 + lane + 32), a1);
        }
        out[(size_t)n * CC + lane]      = a0;
        out[(size_t)n * CC + lane + 32] = a1;
    }
}

// ---------------- fused epilogue --------------------------------------------
__device__ __forceinline__ void matvec64(float va, float vb,
                                         const float* __restrict__ Ws,
                                         const float* __restrict__ bs,
                                         int lane, float& o0, float& o1) {
    float a0 = bs[lane], a1 = bs[lane + 32];
#pragma unroll
    for (int k = 0; k < 32; k++) {
        float vk = __shfl_sync(0xffffffffu, va, k);
        a0 = fmaf(vk, Ws[k * CC + lane], a0);
        a1 = fmaf(vk, Ws[k * CC + lane + 32], a1);
    }
#pragma unroll
    for (int k = 0; k < 32; k++) {
        float vk = __shfl_sync(0xffffffffu, vb, k);
        a0 = fmaf(vk, Ws[(k + 32) * CC + lane], a0);
        a1 = fmaf(vk, Ws[(k + 32) * CC + lane + 32], a1);
    }
    o0 = a0; o1 = a1;
}

__device__ __forceinline__ float warpsum(float v) {
    v += __shfl_xor_sync(0xffffffffu, v, 16);
    v += __shfl_xor_sync(0xffffffffu, v, 8);
    v += __shfl_xor_sync(0xffffffffu, v, 4);
    v += __shfl_xor_sync(0xffffffffu, v, 2);
    v += __shfl_xor_sync(0xffffffffu, v, 1);
    return v;
}

#define OFF_WB  0
#define OFF_WX  4096
#define OFF_W1  8192
#define OFF_W2  12288
#define OFF_W3  14336
#define OFF_VC  14400
#define OFF_BWB 14464
#define OFF_BWX 14528
#define OFF_B1  14592
#define OFF_B2  14656
#define OFF_B3  14688
#define EPI_SMEM_FLOATS 14720
#define EPI_SMEM_BYTES (EPI_SMEM_FLOATS * 4)

__global__ void epilogue_kernel(const float* __restrict__ thetas,
                                const float* __restrict__ Wb, const float* __restrict__ bWb,
                                const float* __restrict__ Wx, const float* __restrict__ bWx,
                                const float* __restrict__ vc,
                                const float* __restrict__ W1, const float* __restrict__ b1,
                                const float* __restrict__ W2, const float* __restrict__ b2,
                                const float* __restrict__ W3, const float* __restrict__ b3,
                                float* __restrict__ out) {
    extern __shared__ float sm[];
    int t = threadIdx.x;
    for (int i = t; i < 4096; i += blockDim.x) {
        sm[OFF_WB + i] = Wb[i];
        sm[OFF_WX + i] = Wx[i];
        sm[OFF_W1 + i] = W1[i];
    }
    for (int i = t; i < 2048; i += blockDim.x) sm[OFF_W2 + i] = W2[i];
    if (t < 64) {
        sm[OFF_W3 + t]  = W3[t];
        sm[OFF_VC + t]  = vc[t];
        sm[OFF_BWB + t] = bWb[t];
        sm[OFF_BWX + t] = bWx[t];
        sm[OFF_B1 + t]  = b1[t];
    }
    if (t < 32) sm[OFF_B2 + t] = b2[t];
    if (t < 2)  sm[OFF_B3 + t] = b3[t];
    __syncthreads();

    float t00 = thetas[0], t01 = thetas[1], t02 = thetas[2], t03 = thetas[3];
    float t10 = thetas[4], t11 = thetas[5], t12 = thetas[6], t13 = thetas[7];
    float c00 = t00;
    float c01 = -3.f * t00 + 3.f * t01;
    float c02 =  3.f * t00 - 6.f * t01 + 3.f * t02;
    float c03 = -1.f * t00 + 3.f * t01 - 3.f * t02 + t03;
    float c10 = t10;
    float c11 = -3.f * t10 + 3.f * t11;
    float c12 =  3.f * t10 - 6.f * t11 + 3.f * t12;
    float c13 = -1.f * t10 + 3.f * t11 - 3.f * t12 + t13;

    const float* sWb = sm + OFF_WB;
    const float* sWx = sm + OFF_WX;
    const float* sW1 = sm + OFF_W1;
    const float* sW2 = sm + OFF_W2;
    const float* sW3 = sm + OFF_W3;
    const float* svc = sm + OFF_VC;

    int lane = threadIdx.x & 31;
    int gw = (blockIdx.x * blockDim.x + threadIdx.x) >> 5;
    int nw = (gridDim.x * blockDim.x) >> 5;

    for (int n = gw; n < NN; n += nw) {
        size_t base = (size_t)n * CC;
        float ha  = g_h [base + lane], hb  = g_h [base + lane + 32];
        float x1a = g_t1[base + lane], x1b = g_t1[base + lane + 32];
        float x2a = g_t2[base + lane], x2b = g_t2[base + lane + 32];
        float x3a = g_t3[base + lane], x3b = g_t3[base + lane + 32];

        float p0a = c00 * ha + c01 * x1a + c02 * x2a + c03 * x3a;
        float p0b = c00 * hb + c01 * x1b + c02 * x2b + c03 * x3b;
        float p1a = c10 * ha + c11 * x1a + c12 * x2a + c13 * x3a;
        float p1b = c10 * hb + c11 * x1b + c12 * x2b + c13 * x3b;

        float pp0a, pp0b, pp1a, pp1b, xpa, xpb;
        matvec64(p0a, p0b, sWb, sm + OFF_BWB, lane, pp0a, pp0b);
        matvec64(p1a, p1b, sWb, sm + OFF_BWB, lane, pp1a, pp1b);
        matvec64(ha, hb, sWx, sm + OFF_BWX, lane, xpa, xpb);

        float s0 = warpsum(tanhf(pp0a + xpa) * svc[lane] +
                           tanhf(pp0b + xpb) * svc[lane + 32]);
        float s1 = warpsum(tanhf(pp1a + xpa) * svc[lane] +
                           tanhf(pp1b + xpb) * svc[lane + 32]);
        float m = fmaxf(s0, s1);
        float e0 = expf(s0 - m), e1 = expf(s1 - m);
        float inv = 1.f / (e0 + e1);
        float a0 = e0 * inv, a1 = e1 * inv;

        float ra = a0 * p0a + a1 * p1a;
        float rb = a0 * p0b + a1 * p1b;

        float y1a, y1b;
        matvec64(ra, rb, sW1, sm + OFF_B1, lane, y1a, y1b);
        y1a = fmaxf(y1a, 0.f); y1b = fmaxf(y1b, 0.f);

        float acc = sm[OFF_B2 + lane];
#pragma unroll
        for (int k = 0; k < 32; k++) {
            float vk = __shfl_sync(0xffffffffu, y1a, k);
            acc = fmaf(vk, sW2[k * 32 + lane], acc);
        }
#pragma unroll
        for (int k = 0; k < 32; k++) {
            float vk = __shfl_sync(0xffffffffu, y1b, k);
            acc = fmaf(vk, sW2[(k + 32) * 32 + lane], acc);
        }
        float y2 = fmaxf(acc, 0.f);

        float q0 = y2 * sW3[lane * 2 + 0];
        float q1 = y2 * sW3[lane * 2 + 1];
        q0 = warpsum(q0);
        q1 = warpsum(q1);
        if (lane == 0) {
            out[(size_t)n * 2 + 0] = sm[OFF_B3 + 0] + q0;
            out[(size_t)n * 2 + 1] = sm[OFF_B3 + 1] + q1;
        }
    }
}

// ---------------- launch ----------------------------------------------------
extern "C" void kernel_launch(void* const* d_in, const int* in_sizes, int n_in,
                              void* d_out, int out_size) {
    const float* x      = (const float*)d_in[0];
    const void*  esrc   = d_in[1];
    const void*  edst   = d_in[2];
    const float* evals  = (const float*)d_in[3];
    const float* Win    = (const float*)d_in[4];
    const float* bin    = (const float*)d_in[5];
    const float* thetas = (const float*)d_in[6];
    const float* Wb     = (const float*)d_in[7];
    const float* bWb    = (const float*)d_in[8];
    const float* Wx     = (const float*)d_in[9];
    const float* bWx    = (const float*)d_in[10];
    const float* vc     = (const float*)d_in[11];
    const float* W1     = (const float*)d_in[12];
    const float* b1     = (const float*)d_in[13];
    const float* W2     = (const float*)d_in[14];
    const float* b2     = (const float*)d_in[15];
    const float* W3     = (const float*)d_in[16];
    const float* b3     = (const float*)d_in[17];
    float* out = (float*)d_out;

    cudaFuncSetAttribute(epilogue_kernel,
                         cudaFuncAttributeMaxDynamicSharedMemorySize,
                         EPI_SMEM_BYTES);

    detect_kernel<<<1, 32>>>((const unsigned int*)esrc);
    zero_cnt_kernel<<<(NN + 255) / 256, 256>>>();
    convert_hist_kernel<<<(EE + 255) / 256, 256>>>(esrc, edst);
    scan_block_kernel<<<NB_SCAN, 512>>>();
    scan_bsum_kernel<<<1, 256>>>();
    add_offsets_kernel<<<(NN + 255) / 256, 256>>>();
    scatter_kernel<<<(EE + 255) / 256, 256>>>(evals);

    gemm_in_kernel<<<1184, 256>>>(x, Win, bin);

    spmm_csr_kernel<0><<<1184, 256>>>();
    spmm_csr_kernel<1><<<1184, 256>>>();
    spmm_csr_kernel<2><<<1184, 256>>>();

    epilogue_kernel<<<444, 256, EPI_SMEM_BYTES>>>(
        thetas, Wb, bWb, Wx, bWx, vc, W1, b1, W2, b2, W3, b3, out);
}